// round 2
// baseline (speedup 1.0000x reference)
#include <cuda_runtime.h>

#define BT 1024
#define NWARP 32
#define RHO_F 1060.0f
#define CCFL_F 0.9f
#define EPS_AF 1e-6f
#define MAX_CTA 96
#define MAX_T 1024

// Per-step publication records (distinct address per (t, cta) — no atomics, no reuse races).
// recR[t][c] = {maxbits, A_last, Q_last, FQ_last}   (ready flag = .x != 0)
// recL[t][c] = {A_first, Q_first, FQ_first, maxbits} (ready flag = .w != 0)
__device__ float4 g_recR[MAX_T][MAX_CTA];
__device__ float4 g_recL[MAX_T][MAX_CTA];

__device__ __forceinline__ float4 ld_acq_v4(const float4* p) {
    float4 v;
    asm volatile("ld.acquire.gpu.global.v4.f32 {%0,%1,%2,%3}, [%4];"
                 : "=f"(v.x), "=f"(v.y), "=f"(v.z), "=f"(v.w) : "l"(p) : "memory");
    return v;
}
__device__ __forceinline__ void st_rel_v4(float4* p, float4 v) {
    asm volatile("st.release.gpu.global.v4.f32 [%0], {%1,%2,%3,%4};"
                 :: "l"(p), "f"(v.x), "f"(v.y), "f"(v.z), "f"(v.w) : "memory");
}
__device__ __forceinline__ float sqrt_fast(float x) {
    float y; asm("sqrt.approx.f32 %0, %1;" : "=f"(y) : "f"(x)); return y;
}

__global__ void sim_init_kernel(int nrec) {
    int i = blockIdx.x * blockDim.x + threadIdx.x;
    float4 z = make_float4(0.f, 0.f, 0.f, 0.f);
    if (i < nrec) {
        ((float4*)g_recR)[i] = z;
        ((float4*)g_recL)[i] = z;
    }
}

__global__ void __launch_bounds__(BT, 1) sim_kernel(
    const float* __restrict__ Rs,
    const float* __restrict__ sim_dat,      // (2, M)
    const float* __restrict__ sdc,          // (11, M)
    const float* __restrict__ input_data,   // (T,)
    const int*   __restrict__ strides,      // (3, 2)
    float*       __restrict__ out,          // (T, 3)
    int M, int T)
{
    __shared__ float sA[2][BT], sQ[2][BT], sF[2][BT];
    __shared__ int   wmax[NWARP];
    __shared__ float bc[9];          // [0]=smax [1]=lam [2]=inflow [3..5]=left AQF [6..8]=right AQF
    __shared__ float sEF[3], sEL[3]; // this-CTA first / last point state (for publication)
    __shared__ float sIn[512];       // input_data cache

    const int tid  = threadIdx.x;
    const int lane = tid & 31;
    const int wid  = tid >> 5;
    const int cta  = blockIdx.x;
    const int nCTA = gridDim.x;
    const int gi   = cta * BT + tid;
    const bool active = gi < M;

    // cache inflow series
    for (int i = tid; i < T; i += BT) sIn[i] = input_data[i];

    const int st0 = strides[0], st1 = strides[2], st2 = strides[4];
    const int en0 = strides[1] - 1, en1 = strides[3] - 1, en2 = strides[5] - 1;
    const int mid0 = (strides[0] + strides[1]) >> 1;
    const int mid1 = (strides[2] + strides[3]) >> 1;
    const int mid2 = (strides[4] + strides[5]) >> 1;

    const bool is_start = active && (gi == st0 || gi == st1 || gi == st2);
    const bool is_end   = active && (gi == en0 || gi == en1 || gi == en2);
    const bool interior = active && gi > 0 && gi < M - 1;
    const int  midv = (gi == mid0) ? 0 : (gi == mid1) ? 1 : (gi == mid2) ? 2 : -1;

    // per-point constants + initial state
    float A = 1.0f, Q = 0.0f, invA0 = 1.0f, beta = 1.0f, Rtot = 1.0f;
    if (active) {
        A = fmaxf(sim_dat[gi], EPS_AF);
        Q = 0.1f * sim_dat[M + gi];
        invA0 = __fdividef(1.0f, sdc[gi] + 0.5f);
        beta = sdc[M + gi] + 1.0f;
        if (is_end) {
            float R1 = sdc[7 * M + gi] + 0.5f;
            float R2 = sdc[8 * M + gi] + 0.5f;
            bool m1 = (gi >= strides[2]) && (gi < strides[3]);
            bool m2 = (gi >= strides[4]) && (gi < strides[5]);
            float rsv[4];
#pragma unroll
            for (int j = 0; j < 4; j++) {
                float x = Rs[j];
                rsv[j] = fmaxf(x, 0.0f) + log1pf(expf(-fabsf(x)));   // softplus
            }
            if (m1)      { R1 *= rsv[0]; R2 *= rsv[1]; }
            else if (m2) { R1 *= rsv[2]; R2 *= rsv[3]; }
            Rtot = R1 + R2;
        }
    }
    const float cc  = beta * (0.5f / RHO_F);
    const float fqc = beta * invA0 * (1.0f / (3.0f * RHO_F));

    // ---- prologue: state-0 derived quantities, publish rec[0] ----
    float sq = 1.0f, FQ = 0.0f, sval = 0.0f;
    if (active) {
        sq = sqrt_fast(A * invA0);
        float u = __fdividef(Q, A);
        float c = sqrt_fast(cc * sq);
        sval = fabsf(u) + c;
        FQ = Q * u + fqc * A * sq;
    }
    sA[0][tid] = A; sQ[0][tid] = Q; sF[0][tid] = FQ;
    if (tid == 0)      { sEF[0] = A; sEF[1] = Q; sEF[2] = FQ; }
    if (tid == BT - 1) { sEL[0] = A; sEL[1] = Q; sEL[2] = FQ; }
    {
        int wv = __reduce_max_sync(0xFFFFFFFFu, __float_as_int(sval));
        if (lane == 0) wmax[wid] = wv;
    }
    __syncthreads();
    if (wid == 0) {
        int v = __reduce_max_sync(0xFFFFFFFFu, wmax[lane]);
        if (lane == 0) {
            float mf = __int_as_float(v);
            st_rel_v4(&g_recL[0][cta], make_float4(sEF[0], sEF[1], sEF[2], mf));
            st_rel_v4(&g_recR[0][cta], make_float4(mf, sEL[0], sEL[1], sEL[2]));
        }
    }

    for (int t = 0; t < T; ++t) {
        const int b = t & 1, nb = b ^ 1;

        // ---- barrier + reduce: warp 0 polls all per-CTA records for step t ----
        if (wid == 0) {
            const int s0 = lane, s1 = lane + 32, s2 = lane + 64;
            const bool n0 = s0 < nCTA, n1 = s1 < nCTA, n2 = s2 < nCTA;
            const bool needL = (lane == 31) && (cta + 1 < nCTA);   // right-neighbor first-point record
            float4 r0, r1, r2, rl;
            unsigned want = (n0 ? 1u : 0u) | (n1 ? 2u : 0u) | (n2 ? 4u : 0u) | (needL ? 8u : 0u);
            unsigned done = 0;
            for (;;) {
                if (n0 && !(done & 1u)) { r0 = ld_acq_v4(&g_recR[t][s0]); if (__float_as_int(r0.x) != 0) done |= 1u; }
                if (n1 && !(done & 2u)) { r1 = ld_acq_v4(&g_recR[t][s1]); if (__float_as_int(r1.x) != 0) done |= 2u; }
                if (n2 && !(done & 4u)) { r2 = ld_acq_v4(&g_recR[t][s2]); if (__float_as_int(r2.x) != 0) done |= 4u; }
                if (needL && !(done & 8u)) { rl = ld_acq_v4(&g_recL[t][cta + 1]); if (__float_as_int(rl.w) != 0) done |= 8u; }
                if (__all_sync(0xFFFFFFFFu, done == want)) break;
            }
            int mb = 0;
            if (n0) mb = max(mb, __float_as_int(r0.x));
            if (n1) mb = max(mb, __float_as_int(r1.x));
            if (n2) mb = max(mb, __float_as_int(r2.x));
            mb = __reduce_max_sync(0xFFFFFFFFu, mb);
            // left-neighbor edge rides in recR[cta-1].yzw — owned by one poll lane
            if (cta > 0) {
                int src = cta - 1;
                if (lane == (src & 31)) {
                    float4 rv = (src >> 5) == 0 ? r0 : ((src >> 5) == 1 ? r1 : r2);
                    bc[3] = rv.y; bc[4] = rv.z; bc[5] = rv.w;
                }
            }
            if (needL) { bc[6] = rl.x; bc[7] = rl.y; bc[8] = rl.z; }
            if (lane == 0) {
                float smax = __int_as_float(mb);
                bc[0] = smax;
                bc[1] = __fdividef(CCFL_F, smax);   // lam = CCFL/smax (DX cancels)
                bc[2] = sIn[t];
            }
        }
        __syncthreads();
        const float smax = bc[0], lam = bc[1], inflow = bc[2];

        // halo from smem (double-buffered) or cluster-edge broadcast
        float Al, Ql, Fl, Ar, Qr, Fr;
        if (tid > 0) { Al = sA[b][tid - 1]; Ql = sQ[b][tid - 1]; Fl = sF[b][tid - 1]; }
        else         { Al = bc[3]; Ql = bc[4]; Fl = bc[5]; }
        if (tid < BT - 1) { Ar = sA[b][tid + 1]; Qr = sQ[b][tid + 1]; Fr = sF[b][tid + 1]; }
        else              { Ar = bc[6]; Qr = bc[7]; Fr = bc[8]; }

        // pre-update pressure (mid output + end BC)
        float P = beta * (sq - 1.0f);
        if (midv >= 0) out[t * 3 + midv] = P;

        // Lax–Friedrichs update
        float h = 0.5f * smax;
        float fhA_R = 0.5f * (Q + Qr) - h * (Ar - A);
        float fhA_L = 0.5f * (Ql + Q) - h * (A - Al);
        float fhQ_R = 0.5f * (FQ + Fr) - h * (Qr - Q);
        float fhQ_L = 0.5f * (Fl + FQ) - h * (Q - Ql);
        float An = interior ? A - lam * (fhA_R - fhA_L) : A;
        float Qn = interior ? Q - lam * (fhQ_R - fhQ_L) : Q;
        if (is_start) Qn = inflow;
        if (is_end)   Qn = __fdividef(P, Rtot);
        An = fmaxf(An, EPS_AF);

        float snew = 0.0f;
        if (active) {
            A = An; Q = Qn;
            sq = sqrt_fast(A * invA0);
            float u = __fdividef(Q, A);
            float c = sqrt_fast(cc * sq);
            snew = fabsf(u) + c;
            FQ = Q * u + fqc * A * sq;
        }

        // publish new state (double-buffered smem — safe without extra barrier)
        sA[nb][tid] = A; sQ[nb][tid] = Q; sF[nb][tid] = FQ;
        if (tid == 0)      { sEF[0] = A; sEF[1] = Q; sEF[2] = FQ; }
        if (tid == BT - 1) { sEL[0] = A; sEL[1] = Q; sEL[2] = FQ; }
        int wv = __reduce_max_sync(0xFFFFFFFFu, __float_as_int(snew));
        if (lane == 0) wmax[wid] = wv;
        __syncthreads();
        if (wid == 0) {
            int v = __reduce_max_sync(0xFFFFFFFFu, wmax[lane]);
            if (lane == 0) {
                float mf = __int_as_float(v);
                st_rel_v4(&g_recL[t + 1][cta], make_float4(sEF[0], sEF[1], sEF[2], mf));
                st_rel_v4(&g_recR[t + 1][cta], make_float4(mf, sEL[0], sEL[1], sEL[2]));
            }
        }
    }
}

extern "C" void kernel_launch(void* const* d_in, const int* in_sizes, int n_in,
                              void* d_out, int out_size) {
    const float* Rs         = (const float*)d_in[0];
    const float* sim_dat    = (const float*)d_in[1];
    const float* sdc        = (const float*)d_in[2];
    const float* input_data = (const float*)d_in[3];
    const int*   strides    = (const int*)d_in[4];

    int M = in_sizes[1] / 2;     // sim_dat is (2, M)
    int T = in_sizes[3];         // input_data length

    int nCTA = (M + BT - 1) / BT;   // 88 for M=90000 — all co-resident (<=148 SMs)

    int nrec = (T + 1) * MAX_CTA;
    sim_init_kernel<<<(nrec + 255) / 256, 256>>>(nrec);
    sim_kernel<<<nCTA, BT>>>(Rs, sim_dat, sdc, input_data, strides, (float*)d_out, M, T);
}